// round 2
// baseline (speedup 1.0000x reference)
#include <cuda_runtime.h>
#include <math.h>

#define N_NODES 40000
#define E_EDGES 640000
#define D_IN    32
#define D_G     64
#define D_F     128

// ---------------- scratch (static device globals; no allocation) ----------------
__device__ float g_h[N_NODES * D_F];                      // projected node features
__device__ float g_agg[N_NODES * D_F];                    // aggregated messages
__device__ float g_messages[(size_t)E_EDGES * D_F];       // per-edge messages (328 MB)
__device__ int   g_rowptr[N_NODES + 1];

// ---------------- K1: h = x @ W_proj + b_proj ----------------
__global__ __launch_bounds__(128) void proj_kernel(const float* __restrict__ x,
                                                   const float* __restrict__ W,
                                                   const float* __restrict__ b) {
    const int f  = threadIdx.x;
    const int nb = blockIdx.x * 8;
    __shared__ float xs[8 * D_IN];
    xs[f]       = x[nb * D_IN + f];
    xs[f + 128] = x[nb * D_IN + f + 128];
    float w[D_IN];
#pragma unroll
    for (int k = 0; k < D_IN; k++) w[k] = W[k * D_F + f];
    const float bias = b[f];
    __syncthreads();
#pragma unroll
    for (int n = 0; n < 8; n++) {
        float acc = bias;
#pragma unroll
        for (int k = 0; k < D_IN; k++) acc = fmaf(xs[n * D_IN + k], w[k], acc);
        g_h[(nb + n) * D_F + f] = acc;
    }
}

// ---------------- K2: row_ptr via binary search on sorted tgt (int32) ----------------
__global__ void rowptr_kernel(const int* __restrict__ tgt) {
    int n = blockIdx.x * blockDim.x + threadIdx.x;
    if (n > N_NODES) return;
    if (n == N_NODES) { g_rowptr[n] = E_EDGES; return; }
    int lo = 0, hi = E_EDGES;
    while (lo < hi) {
        int mid = (lo + hi) >> 1;
        if (tgt[mid] < n) lo = mid + 1; else hi = mid;
    }
    g_rowptr[n] = lo;
}

// ---------------- K3: edge filter MLP + messages + raw attention ----------------
// Tile: 64 edges x 128 feats. Block 256 threads = 8 warps.
// Warp w owns edges w*8..w*8+7; lane owns feats lane*4..lane*4+3 (float4).
__global__ __launch_bounds__(256) void edge_kernel(
    const int* __restrict__ src,
    const float* __restrict__ edge_attr,
    const float* __restrict__ Wf1, const float* __restrict__ bf1,
    const float* __restrict__ Wf2, const float* __restrict__ bf2,
    const float* __restrict__ nbr,
    float* __restrict__ attn_out)
{
    __shared__ float sm[64 * D_F];      // t_s; front 64*64 floats doubles as ean_s
    __shared__ float norm_s[64];
    __shared__ float inv_s[64];
    float* ean_s = sm;
    float* t_s   = sm;

    const int tid   = threadIdx.x;
    const int lane  = tid & 31;
    const int w     = tid >> 5;
    const int ebase = blockIdx.x * 64;

    if (tid < 64) norm_s[tid] = 0.f;
    __syncthreads();

    // --- load edge_attr tile (contiguous 4096 floats), accumulate per-row sumsq ---
    float4 v[4];
    const float4* ea4 = (const float4*)(edge_attr + (size_t)ebase * D_G);
#pragma unroll
    for (int j = 0; j < 4; j++) {
        int p = tid + 256 * j;                 // float4 index 0..1023; row = p>>4
        v[j] = ea4[p];
        float ss = v[j].x * v[j].x + v[j].y * v[j].y + v[j].z * v[j].z + v[j].w * v[j].w;
        atomicAdd(&norm_s[p >> 4], ss);
    }
    __syncthreads();
    if (tid < 64) inv_s[tid] = 1.0f / (sqrtf(norm_s[tid]) + 1e-8f);
    __syncthreads();
#pragma unroll
    for (int j = 0; j < 4; j++) {
        int p = tid + 256 * j;
        float inv = inv_s[p >> 4];
        v[j].x *= inv; v[j].y *= inv; v[j].z *= inv; v[j].w *= inv;
        ((float4*)ean_s)[p] = v[j];
    }
    __syncthreads();

    // --- GEMM1: t = tanh(ean @ Wf1 + bf1), register tile 8 edges x float4 ---
    float4 acc[8];
    {
        float4 b1 = *(const float4*)(bf1 + lane * 4);
#pragma unroll
        for (int i = 0; i < 8; i++) acc[i] = b1;
    }
    for (int k = 0; k < D_G; k++) {
        float4 wk = *(const float4*)(Wf1 + k * D_F + lane * 4);
#pragma unroll
        for (int i = 0; i < 8; i++) {
            float a = ean_s[(w * 8 + i) * D_G + k];   // broadcast across warp
            acc[i].x = fmaf(a, wk.x, acc[i].x);
            acc[i].y = fmaf(a, wk.y, acc[i].y);
            acc[i].z = fmaf(a, wk.z, acc[i].z);
            acc[i].w = fmaf(a, wk.w, acc[i].w);
        }
    }
#pragma unroll
    for (int i = 0; i < 8; i++) {
        acc[i].x = tanhf(acc[i].x); acc[i].y = tanhf(acc[i].y);
        acc[i].z = tanhf(acc[i].z); acc[i].w = tanhf(acc[i].w);
    }
    __syncthreads();                // all ean reads done before overwrite
#pragma unroll
    for (int i = 0; i < 8; i++)
        ((float4*)(t_s + (w * 8 + i) * D_F))[lane] = acc[i];
    __syncthreads();

    // --- GEMM2: filters = t @ Wf2 + bf2 ---
    {
        float4 b2 = *(const float4*)(bf2 + lane * 4);
#pragma unroll
        for (int i = 0; i < 8; i++) acc[i] = b2;
    }
    for (int k = 0; k < D_F; k++) {
        float4 wk = *(const float4*)(Wf2 + k * D_F + lane * 4);
#pragma unroll
        for (int i = 0; i < 8; i++) {
            float a = t_s[(w * 8 + i) * D_F + k];     // broadcast across warp
            acc[i].x = fmaf(a, wk.x, acc[i].x);
            acc[i].y = fmaf(a, wk.y, acc[i].y);
            acc[i].z = fmaf(a, wk.z, acc[i].z);
            acc[i].w = fmaf(a, wk.w, acc[i].w);
        }
    }

    // --- messages = h[src] * filters; attn = messages . nbr_filter ---
    const float4 nbr4 = *(const float4*)(nbr + lane * 4);
    float p[8];
#pragma unroll
    for (int i = 0; i < 8; i++) {
        int e = ebase + w * 8 + i;
        int sn = src[e];
        float4 h4 = *(const float4*)(g_h + (size_t)sn * D_F + lane * 4);
        float4 m;
        m.x = h4.x * acc[i].x; m.y = h4.y * acc[i].y;
        m.z = h4.z * acc[i].z; m.w = h4.w * acc[i].w;
        ((float4*)(g_messages + (size_t)e * D_F))[lane] = m;
        p[i] = m.x * nbr4.x + m.y * nbr4.y + m.z * nbr4.z + m.w * nbr4.w;
    }
#pragma unroll
    for (int off = 16; off; off >>= 1) {
#pragma unroll
        for (int i = 0; i < 8; i++)
            p[i] += __shfl_xor_sync(0xffffffffu, p[i], off);
    }
    if (lane == 0) {
#pragma unroll
        for (int i = 0; i < 8; i++) attn_out[ebase + w * 8 + i] = p[i];
    }
}

// ---------------- K4: per-node segment softmax + weighted aggregate ----------------
__global__ __launch_bounds__(256) void agg_kernel(const float* __restrict__ attn) {
    const int node = (blockIdx.x * blockDim.x + threadIdx.x) >> 5;
    const int lane = threadIdx.x & 31;
    if (node >= N_NODES) return;
    const int s = g_rowptr[node];
    const int e = g_rowptr[node + 1];

    float m = -INFINITY;
    for (int j = s + lane; j < e; j += 32) m = fmaxf(m, attn[j]);
#pragma unroll
    for (int off = 16; off; off >>= 1) m = fmaxf(m, __shfl_xor_sync(0xffffffffu, m, off));

    float ssum = 0.f;
    for (int j = s + lane; j < e; j += 32) ssum += expf(attn[j] - m);
#pragma unroll
    for (int off = 16; off; off >>= 1) ssum += __shfl_xor_sync(0xffffffffu, ssum, off);
    const float inv = (e > s) ? 1.0f / ssum : 0.0f;

    float4 acc = make_float4(0.f, 0.f, 0.f, 0.f);
    for (int j = s; j < e; j++) {
        float wgt = expf(attn[j] - m) * inv;               // attn[j] broadcast (L1)
        float4 mm = ((const float4*)(g_messages + (size_t)j * D_F))[lane];
        acc.x = fmaf(wgt, mm.x, acc.x);
        acc.y = fmaf(wgt, mm.y, acc.y);
        acc.z = fmaf(wgt, mm.z, acc.z);
        acc.w = fmaf(wgt, mm.w, acc.w);
    }
    ((float4*)(g_agg + (size_t)node * D_F))[lane] = acc;
}

// ---------------- K5: out = tanh(agg @ Wo1 + bo1) @ Wo2 + bo2 ----------------
__global__ __launch_bounds__(256) void out_kernel(
    const float* __restrict__ Wo1, const float* __restrict__ bo1,
    const float* __restrict__ Wo2, const float* __restrict__ bo2,
    float* __restrict__ out)
{
    __shared__ float sm[64 * D_F];     // agg_s, then t_s (aliased)
    const int tid  = threadIdx.x;
    const int lane = tid & 31;
    const int w    = tid >> 5;
    const int nb   = blockIdx.x * 64;

    // stage agg tile (contiguous 8192 floats)
    const float4* src4 = (const float4*)(g_agg + (size_t)nb * D_F);
#pragma unroll
    for (int j = 0; j < 8; j++)
        ((float4*)sm)[tid + 256 * j] = src4[tid + 256 * j];
    __syncthreads();

    // GEMM1: t = tanh(agg @ Wo1 + bo1)
    float4 acc[8];
    {
        float4 b1 = *(const float4*)(bo1 + lane * 4);
#pragma unroll
        for (int i = 0; i < 8; i++) acc[i] = b1;
    }
    for (int k = 0; k < D_F; k++) {
        float4 wk = *(const float4*)(Wo1 + k * D_F + lane * 4);
#pragma unroll
        for (int i = 0; i < 8; i++) {
            float a = sm[(w * 8 + i) * D_F + k];
            acc[i].x = fmaf(a, wk.x, acc[i].x);
            acc[i].y = fmaf(a, wk.y, acc[i].y);
            acc[i].z = fmaf(a, wk.z, acc[i].z);
            acc[i].w = fmaf(a, wk.w, acc[i].w);
        }
    }
#pragma unroll
    for (int i = 0; i < 8; i++) {
        acc[i].x = tanhf(acc[i].x); acc[i].y = tanhf(acc[i].y);
        acc[i].z = tanhf(acc[i].z); acc[i].w = tanhf(acc[i].w);
    }
    __syncthreads();
#pragma unroll
    for (int i = 0; i < 8; i++)
        ((float4*)(sm + (w * 8 + i) * D_F))[lane] = acc[i];
    __syncthreads();

    // GEMM2: out[64][32] = t @ Wo2 + bo2 ; lane = output feature (32 lanes)
    float o[8];
    {
        float b2 = bo2[lane];
#pragma unroll
        for (int i = 0; i < 8; i++) o[i] = b2;
    }
    for (int k = 0; k < D_F; k++) {
        float wo = Wo2[k * D_IN + lane];
#pragma unroll
        for (int i = 0; i < 8; i++)
            o[i] = fmaf(sm[(w * 8 + i) * D_F + k], wo, o[i]);
    }
#pragma unroll
    for (int i = 0; i < 8; i++)
        out[(size_t)(nb + w * 8 + i) * D_IN + lane] = o[i];
}

// ---------------- launch ----------------
extern "C" void kernel_launch(void* const* d_in, const int* in_sizes, int n_in,
                              void* d_out, int out_size) {
    const float* x         = (const float*)d_in[0];
    const int*   edge_index= (const int*)d_in[1];     // int32 (JAX x64 disabled)
    const float* edge_attr = (const float*)d_in[2];
    const float* W_proj    = (const float*)d_in[3];
    const float* b_proj    = (const float*)d_in[4];
    const float* Wf1       = (const float*)d_in[5];
    const float* bf1       = (const float*)d_in[6];
    const float* Wf2       = (const float*)d_in[7];
    const float* bf2       = (const float*)d_in[8];
    const float* nbr       = (const float*)d_in[9];
    const float* Wo1       = (const float*)d_in[10];
    const float* bo1       = (const float*)d_in[11];
    const float* Wo2       = (const float*)d_in[12];
    const float* bo2       = (const float*)d_in[13];

    float* out      = (float*)d_out;
    float* attn_out = out + (size_t)N_NODES * D_IN;   // tuple (out, attn) concat

    const int* src = edge_index;            // edge_index[0]
    const int* tgt = edge_index + E_EDGES;  // edge_index[1]

    proj_kernel<<<N_NODES / 8, 128>>>(x, W_proj, b_proj);
    rowptr_kernel<<<(N_NODES + 1 + 255) / 256, 256>>>(tgt);
    edge_kernel<<<E_EDGES / 64, 256>>>(src, edge_attr, Wf1, bf1, Wf2, bf2, nbr, attn_out);
    agg_kernel<<<(N_NODES * 32) / 256, 256>>>(attn_out);
    out_kernel<<<N_NODES / 64, 256>>>(Wo1, bo1, Wo2, bo2, out);
}